// round 1
// baseline (speedup 1.0000x reference)
#include <cuda_runtime.h>
#include <math.h>

// Scratch: 3 x 64MB device globals (allocation-free rule)
__device__ float g_Z[32L * 512 * 1024];
__device__ float g_S[32L * 512 * 1024];
__device__ float g_C[32L * 512 * 1024];

#define BM 128
#define BN 128
#define BK 16

// Generic fp32 tiled GEMM:
//   C[bz][m,n] = sum_seg sum_k Aseg[bz][m,k] * Bseg[bz][n or (k,n)]
// BNC=false: B is "NT" (k-contiguous rows, row stride ldb)  -> C = A * B^T
// BNC=true : B is "NN" (n-contiguous rows, k stride  ldb)   -> C = A * B
// DOTANH: epilogue v = tanhf(v + bias[n])
// NSEG=2: accumulate a second (A1,B1) pass (for concat([c,q]) @ W_out^T)
template<bool BNC, bool DOTANH, int NSEG>
__global__ __launch_bounds__(256, 2)
void sgemm_kernel(const float* __restrict__ A0, const float* __restrict__ B0,
                  const float* __restrict__ A1, const float* __restrict__ B1,
                  int K, long lda, long ldb,
                  long sA, long sB, long sC,
                  float* __restrict__ C, int ldc,
                  const float* __restrict__ bias)
{
    __shared__ float As[BK][BM + 4];
    __shared__ float Bs[BK][BN + 4];

    const int tid = threadIdx.x;
    const int tx = tid & 15;          // n micro-tile
    const int ty = tid >> 4;          // m micro-tile
    const long m0 = (long)blockIdx.y * BM;
    const long n0 = (long)blockIdx.x * BN;
    const long bz = blockIdx.z;

    float acc[8][8];
#pragma unroll
    for (int i = 0; i < 8; i++)
#pragma unroll
        for (int j = 0; j < 8; j++) acc[i][j] = 0.0f;

    const int arow = tid >> 2;          // 0..63
    const int ac4  = (tid & 3) * 4;     // 0,4,8,12

#pragma unroll
    for (int seg = 0; seg < NSEG; ++seg) {
        const float* A = (seg == 0 ? A0 : A1) + bz * sA + m0 * lda;
        const float* B = (seg == 0 ? B0 : B1) + bz * sB;

        for (int kt = 0; kt < K; kt += BK) {
            // ---- load A tile (k-contiguous), store transposed As[k][m]
#pragma unroll
            for (int r = 0; r < 2; ++r) {
                const int row = arow + r * 64;
                float4 v = *(const float4*)(A + (long)row * lda + kt + ac4);
                As[ac4 + 0][row] = v.x;
                As[ac4 + 1][row] = v.y;
                As[ac4 + 2][row] = v.z;
                As[ac4 + 3][row] = v.w;
            }
            if (BNC) {
                // B element (k,n) at B[k*ldb + n]; n contiguous
                const int kr = tid >> 5;          // 0..7
                const int nc = (tid & 31) * 4;    // 0..124
#pragma unroll
                for (int r = 0; r < 2; ++r) {
                    const int k = kr + r * 8;
                    float4 v = *(const float4*)(B + (long)(kt + k) * ldb + n0 + nc);
                    *(float4*)&Bs[k][nc] = v;
                }
            } else {
                // B row n is k-contiguous at B[n*ldb + k]
#pragma unroll
                for (int r = 0; r < 2; ++r) {
                    const int row = arow + r * 64;   // n index
                    float4 v = *(const float4*)(B + (n0 + row) * ldb + kt + ac4);
                    Bs[ac4 + 0][row] = v.x;
                    Bs[ac4 + 1][row] = v.y;
                    Bs[ac4 + 2][row] = v.z;
                    Bs[ac4 + 3][row] = v.w;
                }
            }
            __syncthreads();

#pragma unroll
            for (int kk = 0; kk < BK; ++kk) {
                float a[8], b[8];
                *(float4*)&a[0] = *(const float4*)&As[kk][ty * 8];
                *(float4*)&a[4] = *(const float4*)&As[kk][ty * 8 + 4];
                *(float4*)&b[0] = *(const float4*)&Bs[kk][tx * 8];
                *(float4*)&b[4] = *(const float4*)&Bs[kk][tx * 8 + 4];
#pragma unroll
                for (int i = 0; i < 8; i++)
#pragma unroll
                    for (int j = 0; j < 8; j++)
                        acc[i][j] = fmaf(a[i], b[j], acc[i][j]);
            }
            __syncthreads();
        }
    }

    float* Cp = C + bz * sC + (m0 + ty * 8) * ldc + n0 + tx * 8;
#pragma unroll
    for (int i = 0; i < 8; i++) {
#pragma unroll
        for (int j = 0; j < 8; j += 4) {
            float4 v;
            v.x = acc[i][j + 0];
            v.y = acc[i][j + 1];
            v.z = acc[i][j + 2];
            v.w = acc[i][j + 3];
            if (DOTANH) {
                const long nb = n0 + tx * 8 + j;
                v.x = tanhf(v.x + bias[nb + 0]);
                v.y = tanhf(v.y + bias[nb + 1]);
                v.z = tanhf(v.z + bias[nb + 2]);
                v.w = tanhf(v.w + bias[nb + 3]);
            }
            *(float4*)(Cp + (long)i * ldc + j) = v;
        }
    }
}

// Row softmax over S=1024 with the reference's (score==0 -> -inf) fill.
__global__ void softmax_kernel(float* __restrict__ S)
{
    const long row = blockIdx.x;
    float* p = S + (row << 10);
    const int tid = threadIdx.x;   // 256 threads, 4 elems each

    float v[4];
    float mx = -INFINITY;
#pragma unroll
    for (int i = 0; i < 4; i++) {
        float x = p[tid + (i << 8)];
        if (x == 0.0f) x = -INFINITY;
        v[i] = x;
        mx = fmaxf(mx, x);
    }

    __shared__ float red[8];
#pragma unroll
    for (int o = 16; o; o >>= 1) mx = fmaxf(mx, __shfl_xor_sync(0xffffffffu, mx, o));
    if ((tid & 31) == 0) red[tid >> 5] = mx;
    __syncthreads();
    const float m = fmaxf(fmaxf(fmaxf(red[0], red[1]), fmaxf(red[2], red[3])),
                          fmaxf(fmaxf(red[4], red[5]), fmaxf(red[6], red[7])));
    __syncthreads();

    float s = 0.0f;
#pragma unroll
    for (int i = 0; i < 4; i++) { v[i] = expf(v[i] - m); s += v[i]; }
#pragma unroll
    for (int o = 16; o; o >>= 1) s += __shfl_xor_sync(0xffffffffu, s, o);
    if ((tid & 31) == 0) red[tid >> 5] = s;
    __syncthreads();
    const float tot = red[0] + red[1] + red[2] + red[3] + red[4] + red[5] + red[6] + red[7];
    const float inv = 1.0f / tot;
#pragma unroll
    for (int i = 0; i < 4; i++) p[tid + (i << 8)] = v[i] * inv;
}

extern "C" void kernel_launch(void* const* d_in, const int* in_sizes, int n_in,
                              void* d_out, int out_size)
{
    const float* query = (const float*)d_in[0];   // [B,T,H]
    const float* enc   = (const float*)d_in[1];   // [S,B,H]
    // d_in[2] = src_lengths (unused by the reference's math)
    const float* W_in  = (const float*)d_in[3];   // [H,H]
    const float* W_out = (const float*)d_in[4];   // [H,2H]
    const float* b_out = (const float*)d_in[5];   // [H]
    float* out = (float*)d_out;                   // [B,T,H]

    float *Z, *S, *Cc;
    cudaGetSymbolAddress((void**)&Z,  g_Z);
    cudaGetSymbolAddress((void**)&S,  g_S);
    cudaGetSymbolAddress((void**)&Cc, g_C);

    const long B = 32, T = 512, Sq = 1024, H = 1024;
    dim3 thr(256);

    // 1) Z = Q @ W_in^T     (M=16384, N=1024, K=1024)
    sgemm_kernel<false, false, 1><<<dim3(8, 128, 1), thr>>>(
        query, W_in, nullptr, nullptr,
        1024, H, H, 0, 0, 0, Z, 1024, nullptr);

    // 2) scores[b] = Z[b] @ enc[:,b,:]^T   (batched, M=512, N=1024, K=1024)
    sgemm_kernel<false, false, 1><<<dim3(8, 4, 32), thr>>>(
        Z, enc, nullptr, nullptr,
        1024, H, B * H, T * H, H, T * Sq, S, 1024, nullptr);

    // 3) softmax over S (with ==0 -> -inf fill)
    softmax_kernel<<<16384, 256>>>(S);

    // 4) c[b] = P[b] @ enc[:,b,:]          (batched NN, M=512, N=1024, K=1024)
    sgemm_kernel<true, false, 1><<<dim3(8, 4, 32), thr>>>(
        S, enc, nullptr, nullptr,
        1024, Sq, B * H, T * Sq, H, T * H, Cc, 1024, nullptr);

    // 5) out = tanh(c @ W1^T + q @ W2^T + b)   (M=16384, N=1024, K=1024+1024)
    sgemm_kernel<false, true, 2><<<dim3(8, 128, 1), thr>>>(
        Cc, W_out, query, W_out + 1024,
        1024, H, 2 * H, 0, 0, 0, out, 1024, b_out);
}

// round 4
// speedup vs baseline: 2.8988x; 2.8988x over previous
#include <cuda_runtime.h>
#include <cuda_bf16.h>
#include <cstdint>
#include <math.h>

// tcgen05 is only available in the arch-specific ("a") compilation pass.
#if defined(__CUDA_ARCH_FEAT_SM103_ALL) || defined(__CUDA_ARCH_FEAT_SM100_ALL) || \
    defined(__CUDA_ARCH_FEAT_SM110_ALL) || defined(__CUDA_ARCH_FEAT_SM101_ALL)
#define HAS_TCGEN05 1
#else
#define HAS_TCGEN05 0
#endif

// ---------------- scratch (allocation-free rule) ----------------
__device__ float g_Z[32L * 512 * 1024];      // 64MB
__device__ float g_S[32L * 512 * 1024];      // 64MB
__device__ float g_C[32L * 512 * 1024];      // 64MB
__device__ float g_encT[32L * 1024 * 1024];  // 128MB  [b][h][s]

#if HAS_TCGEN05
// ---------------- PTX helpers ----------------
__device__ __forceinline__ uint32_t smem_u32(const void* p) {
    uint32_t a;
    asm("{ .reg .u64 t; cvta.to.shared.u64 t, %1; cvt.u32.u64 %0, t; }" : "=r"(a) : "l"(p));
    return a;
}
__device__ __forceinline__ uint32_t elect_one() {
    uint32_t pred;
    asm volatile("{\n\t.reg .pred p;\n\telect.sync _|p, 0xFFFFFFFF;\n\tselp.b32 %0, 1, 0, p;\n\t}"
                 : "=r"(pred));
    return pred;
}

#define MBARRIER_INIT(addr, cnt) \
    asm volatile("mbarrier.init.shared.b64 [%0], %1;" :: "r"(addr), "r"(cnt) : "memory")

#define MBARRIER_WAIT_PARITY(mbar_smem_addr, phase_parity) do { \
    uint32_t _mbar = (uint32_t)(mbar_smem_addr); \
    uint32_t _parity = (uint32_t)(phase_parity); \
    uint32_t _done; \
    asm volatile( \
        "{\n\t.reg .pred p;\n\t" \
        "mbarrier.try_wait.parity.acquire.cta.shared::cta.b64 p, [%1], %2;\n\t" \
        "selp.b32 %0, 1, 0, p;\n\t}" \
        : "=r"(_done) : "r"(_mbar), "r"(_parity) : "memory"); \
    if (!_done) { \
        asm volatile( \
            "{\n\t.reg .pred P1;\n\t" \
            "WAIT_LOOP_%=:\n\t" \
            "mbarrier.try_wait.parity.acquire.cta.shared::cta.b64 P1, [%0], %1, 0x989680;\n\t" \
            "@P1 bra.uni WAIT_DONE_%=;\n\t" \
            "bra.uni WAIT_LOOP_%=;\n\t" \
            "WAIT_DONE_%=:\n\t}" \
            :: "r"(_mbar), "r"(_parity) : "memory"); \
    } \
} while (0)

#define TCGEN05_ALLOC(smem_addr, n) \
    asm volatile("tcgen05.alloc.cta_group::1.sync.aligned.shared::cta.b32 [%0], %1;" \
                 :: "r"((uint32_t)(smem_addr)), "r"((uint32_t)(n)) : "memory")
#define TCGEN05_DEALLOC(tm, n) \
    asm volatile("tcgen05.dealloc.cta_group::1.sync.aligned.b32 %0, %1;" :: "r"(tm), "r"((uint32_t)(n)))
#define TCGEN05_RELINQ() \
    asm volatile("tcgen05.relinquish_alloc_permit.cta_group::1.sync.aligned;")
#define TCGEN05_COMMIT(mb) \
    asm volatile("tcgen05.commit.cta_group::1.mbarrier::arrive::one.shared::cluster.b64 [%0];" \
                 :: "r"((uint32_t)(mb)) : "memory")
#define TCGEN05_FENCE_AFTER() asm volatile("tcgen05.fence::after_thread_sync;" ::: "memory")
#define TCGEN05_WAIT_LD()     asm volatile("tcgen05.wait::ld.sync.aligned;" ::: "memory")
#define FENCE_PROXY_ASYNC()   asm volatile("fence.proxy.async.shared::cta;" ::: "memory")

#define TCGEN05_LD_X32(r, tm) \
    asm volatile( \
        "tcgen05.ld.sync.aligned.32x32b.x32.b32 " \
        "{%0, %1, %2, %3, %4, %5, %6, %7, %8, %9, %10, %11, %12, %13, %14, %15, " \
        " %16, %17, %18, %19, %20, %21, %22, %23, %24, %25, %26, %27, %28, %29, %30, %31}, [%32];" \
        : "=r"((r)[0]),  "=r"((r)[1]),  "=r"((r)[2]),  "=r"((r)[3]), \
          "=r"((r)[4]),  "=r"((r)[5]),  "=r"((r)[6]),  "=r"((r)[7]), \
          "=r"((r)[8]),  "=r"((r)[9]),  "=r"((r)[10]), "=r"((r)[11]), \
          "=r"((r)[12]), "=r"((r)[13]), "=r"((r)[14]), "=r"((r)[15]), \
          "=r"((r)[16]), "=r"((r)[17]), "=r"((r)[18]), "=r"((r)[19]), \
          "=r"((r)[20]), "=r"((r)[21]), "=r"((r)[22]), "=r"((r)[23]), \
          "=r"((r)[24]), "=r"((r)[25]), "=r"((r)[26]), "=r"((r)[27]), \
          "=r"((r)[28]), "=r"((r)[29]), "=r"((r)[30]), "=r"((r)[31]) \
        : "r"(tm))

// SW128 SMEM descriptor (Blackwell): layout=2, version=1, SBO=64, LBO=1
static constexpr uint64_t DESC_BASE =
    (uint64_t(2) << 61) | (uint64_t(1) << 46) | (uint64_t(64) << 32) | (uint64_t(1) << 16);
__device__ __forceinline__ uint64_t make_desc(uint32_t addr) {
    return DESC_BASE | ((uint64_t)(addr >> 4) & 0x3FFF);
}

// cg1 SS bf16 MMA (f32 accum)
__device__ __forceinline__ void mma_ss(uint32_t d, uint64_t ad, uint64_t bd,
                                       uint32_t idesc, bool acc) {
    uint32_t e = acc ? 1u : 0u;
    asm volatile(
        "{\n\t.reg .pred p;\n\tsetp.ne.u32 p, %4, 0;\n\t"
        "tcgen05.mma.cta_group::1.kind::f16 [%0], %1, %2, %3, {%5, %5, %5, %5}, p;\n\t}"
        :: "r"(d), "l"(ad), "l"(bd), "r"(idesc), "r"(e), "r"(0u) : "memory");
}

// idesc: dtype=F32, a=BF16, b=BF16, N=128, M=128 (K-major both)
static constexpr uint32_t IDESC = (1u << 4) | (1u << 7) | (1u << 10) | (16u << 17) | (8u << 24);

// ---------------- tile loader: fp32 -> NSPLIT bf16 planes, SW128 swizzled ----------------
// tile = 128 rows x 64 cols; planes spaced 16KB apart starting at s0.
template <int NSPLIT>
__device__ __forceinline__ void load_tile(char* s0, const float* __restrict__ g,
                                          long ld, int tid) {
    const int grp = tid >> 3;     // 0..31 (row group)
    const int c8  = tid & 7;      // 8 fp32 elements each
#pragma unroll
    for (int p = 0; p < 4; ++p) {
        const int r = grp + (p << 5);
        const float* src = g + (long)r * ld + (c8 << 3);
        const float4 v0 = *(const float4*)(src);
        const float4 v1 = *(const float4*)(src + 4);
        const float x[8] = {v0.x, v0.y, v0.z, v0.w, v1.x, v1.y, v1.z, v1.w};
        unsigned w0[4], w1[4], w2[4];
#pragma unroll
        for (int j = 0; j < 4; ++j) {
            const float a = x[2 * j], b = x[2 * j + 1];
            const __nv_bfloat16 a0 = __float2bfloat16_rn(a);
            const __nv_bfloat16 b0 = __float2bfloat16_rn(b);
            const float ar = a - __bfloat162float(a0);
            const float br = b - __bfloat162float(b0);
            const __nv_bfloat16 a1 = __float2bfloat16_rn(ar);
            const __nv_bfloat16 b1 = __float2bfloat16_rn(br);
            __nv_bfloat162 p0 = __halves2bfloat162(a0, b0);
            __nv_bfloat162 p1 = __halves2bfloat162(a1, b1);
            w0[j] = *(unsigned*)&p0;
            w1[j] = *(unsigned*)&p1;
            if (NSPLIT == 3) {
                const float ar2 = ar - __bfloat162float(a1);
                const float br2 = br - __bfloat162float(b1);
                __nv_bfloat162 p2 =
                    __halves2bfloat162(__float2bfloat16_rn(ar2), __float2bfloat16_rn(br2));
                w2[j] = *(unsigned*)&p2;
            }
        }
        const uint32_t bo = (r << 7) + (c8 << 4);
        const uint32_t sw = bo ^ ((bo >> 3) & 0x70);
        *(uint4*)(s0 + sw)         = make_uint4(w0[0], w0[1], w0[2], w0[3]);
        *(uint4*)(s0 + 16384 + sw) = make_uint4(w1[0], w1[1], w1[2], w1[3]);
        if (NSPLIT == 3)
            *(uint4*)(s0 + 32768 + sw) = make_uint4(w2[0], w2[1], w2[2], w2[3]);
    }
}
#endif  // HAS_TCGEN05

// ---------------- main GEMM ----------------
// C[bz][m,n] (+= over NSEG segs) = sum_k A[m,k] * B[n,k]   (both operands K-contiguous)
// EPI: 0 = fp32 store, 1 = tanh(x + bias[n]) store.
// Arch-feature pass: tcgen05 split-bf16; otherwise: fp32 FFMA fallback (same semantics).
template <int NSPLIT, int NSEG, int EPI>
__global__ void __launch_bounds__(256, 1)
mma_gemm(const float* A0, const float* B0, const float* A1, const float* B1,
         int K64, long lda, long ldb, long sA, long sB, long sC,
         float* __restrict__ C, int ldc, const float* __restrict__ bias)
{
    extern __shared__ char smem[];
    const int tid = threadIdx.x;
    const long m0 = (long)blockIdx.y * 128;
    const long n0 = (long)blockIdx.x * 128;
    const long bz = blockIdx.z;

#if HAS_TCGEN05
    constexpr int ARR   = 16384;
    constexpr int STAGE = NSPLIT * 2 * ARR;
    const uint32_t sb = smem_u32(smem);
    const int wid = tid >> 5, lid = tid & 31;

    if (wid == 0) TCGEN05_ALLOC(sb, 128);
    __syncthreads();
    uint32_t tmem;
    asm volatile("ld.shared.b32 %0, [%1];" : "=r"(tmem) : "r"(sb));
    if (tid == 0) { MBARRIER_INIT(sb + 8, 1); MBARRIER_INIT(sb + 16, 1); }
    __syncthreads();

    const int total = NSEG * K64;
    int ph0 = 0, ph1 = 0;

    // prologue: load chunk 0 into stage 0
    {
        char* st = smem + 1024;
        load_tile<NSPLIT>(st, A0 + bz * sA + m0 * lda, lda, tid);
        load_tile<NSPLIT>(st + NSPLIT * ARR, B0 + bz * sB + n0 * ldb, ldb, tid);
        FENCE_PROXY_ASYNC();
        __syncthreads();
    }

#pragma unroll 1
    for (int c = 0; c < total; ++c) {
        const int s = c & 1;
        if (wid == 0) {
            if (elect_one()) {
                const uint32_t stb = sb + 1024 + s * STAGE;
                uint64_t dA[3], dB[3];
#pragma unroll
                for (int i = 0; i < NSPLIT; ++i) {
                    dA[i] = make_desc(stb + i * ARR);
                    dB[i] = make_desc(stb + (NSPLIT + i) * ARR);
                }
#pragma unroll
                for (int k = 0; k < 4; ++k) {
                    const uint64_t off = (uint64_t)(k * 2);
                    const bool first = (c == 0) && (k == 0);
                    if (NSPLIT == 3) {
                        mma_ss(tmem, dA[2] + off, dB[0] + off, IDESC, !first);
                        mma_ss(tmem, dA[0] + off, dB[2] + off, IDESC, true);
                        mma_ss(tmem, dA[1] + off, dB[1] + off, IDESC, true);
                        mma_ss(tmem, dA[1] + off, dB[0] + off, IDESC, true);
                        mma_ss(tmem, dA[0] + off, dB[1] + off, IDESC, true);
                        mma_ss(tmem, dA[0] + off, dB[0] + off, IDESC, true);
                    } else {
                        mma_ss(tmem, dA[1] + off, dB[0] + off, IDESC, !first);
                        mma_ss(tmem, dA[0] + off, dB[1] + off, IDESC, true);
                        mma_ss(tmem, dA[0] + off, dB[0] + off, IDESC, true);
                    }
                }
                TCGEN05_COMMIT(sb + 8 + s * 8);
            }
        }
        // load next chunk into the other stage while MMAs run
        if (c + 1 < total) {
            const int s2 = (c + 1) & 1;
            if (c + 1 >= 2) {
                if (s2 == 0) { MBARRIER_WAIT_PARITY(sb + 8, ph0); ph0 ^= 1; }
                else         { MBARRIER_WAIT_PARITY(sb + 16, ph1); ph1 ^= 1; }
            }
            const int cn = c + 1;
            const int seg = (NSEG == 2) ? (int)(cn >= K64) : 0;
            const long kt = (long)(cn - seg * K64) << 6;
            const float* Ag = (seg ? A1 : A0) + bz * sA + m0 * lda + kt;
            const float* Bg = (seg ? B1 : B0) + bz * sB + n0 * ldb + kt;
            char* st = smem + 1024 + s2 * STAGE;
            load_tile<NSPLIT>(st, Ag, lda, tid);
            load_tile<NSPLIT>(st + NSPLIT * ARR, Bg, ldb, tid);
            FENCE_PROXY_ASYNC();
            __syncthreads();
        }
    }

    // wait for last chunk's MMAs
    {
        const int sl = (total - 1) & 1;
        if (sl == 0) { MBARRIER_WAIT_PARITY(sb + 8, ph0); }
        else         { MBARRIER_WAIT_PARITY(sb + 16, ph1); }
    }
    TCGEN05_FENCE_AFTER();

    if (wid < 4) {
        const long m = m0 + wid * 32 + lid;
        float* Crow = C + bz * sC + m * ldc + n0;
#pragma unroll 1
        for (int b4 = 0; b4 < 4; ++b4) {
            uint32_t r[32];
            TCGEN05_LD_X32(r, tmem + b4 * 32);
            TCGEN05_WAIT_LD();
#pragma unroll
            for (int j = 0; j < 32; j += 4) {
                float4 v;
                v.x = __uint_as_float(r[j + 0]);
                v.y = __uint_as_float(r[j + 1]);
                v.z = __uint_as_float(r[j + 2]);
                v.w = __uint_as_float(r[j + 3]);
                if (EPI == 1) {
                    const float* bb = bias + n0 + b4 * 32 + j;
                    v.x = tanhf(v.x + bb[0]);
                    v.y = tanhf(v.y + bb[1]);
                    v.z = tanhf(v.z + bb[2]);
                    v.w = tanhf(v.w + bb[3]);
                }
                *(float4*)(Crow + b4 * 32 + j) = v;
            }
        }
    }
    __syncthreads();
    if (wid == 0) {
        TCGEN05_RELINQ();
        TCGEN05_DEALLOC(tmem, 128);
    }

#else  // ---------------- fp32 FFMA fallback (non-"a" pass) ----------------
    float (*As)[132] = (float(*)[132])smem;                       // [16][132]
    float (*Bs)[132] = (float(*)[132])(smem + 16 * 132 * 4);      // [16][132]

    const int tx = tid & 15;
    const int ty = tid >> 4;
    const int K = K64 << 6;

    float acc[8][8];
#pragma unroll
    for (int i = 0; i < 8; i++)
#pragma unroll
        for (int j = 0; j < 8; j++) acc[i][j] = 0.0f;

    const int arow = tid >> 2;
    const int ac4  = (tid & 3) * 4;

#pragma unroll
    for (int seg = 0; seg < NSEG; ++seg) {
        const float* A = (seg == 0 ? A0 : A1) + bz * sA + m0 * lda;
        const float* B = (seg == 0 ? B0 : B1) + bz * sB + n0 * ldb;

        for (int kt = 0; kt < K; kt += 16) {
#pragma unroll
            for (int r = 0; r < 2; ++r) {
                const int row = arow + r * 64;
                float4 va = *(const float4*)(A + (long)row * lda + kt + ac4);
                As[ac4 + 0][row] = va.x;
                As[ac4 + 1][row] = va.y;
                As[ac4 + 2][row] = va.z;
                As[ac4 + 3][row] = va.w;
                float4 vb = *(const float4*)(B + (long)row * ldb + kt + ac4);
                Bs[ac4 + 0][row] = vb.x;
                Bs[ac4 + 1][row] = vb.y;
                Bs[ac4 + 2][row] = vb.z;
                Bs[ac4 + 3][row] = vb.w;
            }
            __syncthreads();

#pragma unroll
            for (int kk = 0; kk < 16; ++kk) {
                float a[8], b[8];
                *(float4*)&a[0] = *(const float4*)&As[kk][ty * 8];
                *(float4*)&a[4] = *(const float4*)&As[kk][ty * 8 + 4];
                *(float4*)&b[0] = *(const float4*)&Bs[kk][tx * 8];
                *(float4*)&b[4] = *(const float4*)&Bs[kk][tx * 8 + 4];
#pragma unroll
                for (int i = 0; i < 8; i++)
#pragma unroll
                    for (int j = 0; j < 8; j++)
                        acc[i][j] = fmaf(a[i], b[j], acc[i][j]);
            }
            __syncthreads();
        }
    }

    float* Cp = C + bz * sC + (m0 + ty * 8) * ldc + n0 + tx * 8;
#pragma unroll
    for (int i = 0; i < 8; i++) {
#pragma unroll
        for (int j = 0; j < 8; j += 4) {
            float4 v;
            v.x = acc[i][j + 0];
            v.y = acc[i][j + 1];
            v.z = acc[i][j + 2];
            v.w = acc[i][j + 3];
            if (EPI == 1) {
                const long nb = n0 + tx * 8 + j;
                v.x = tanhf(v.x + bias[nb + 0]);
                v.y = tanhf(v.y + bias[nb + 1]);
                v.z = tanhf(v.z + bias[nb + 2]);
                v.w = tanhf(v.w + bias[nb + 3]);
            }
            *(float4*)(Cp + (long)i * ldc + j) = v;
        }
    }
#endif
}

// ---------------- softmax over S=1024 (with ==0 -> -inf fill) ----------------
__global__ void softmax_kernel(float* __restrict__ S)
{
    const long row = blockIdx.x;
    float* p = S + (row << 10);
    const int tid = threadIdx.x;

    float v[4];
    float mx = -INFINITY;
#pragma unroll
    for (int i = 0; i < 4; i++) {
        float x = p[tid + (i << 8)];
        if (x == 0.0f) x = -INFINITY;
        v[i] = x;
        mx = fmaxf(mx, x);
    }
    __shared__ float red[8];
#pragma unroll
    for (int o = 16; o; o >>= 1) mx = fmaxf(mx, __shfl_xor_sync(0xffffffffu, mx, o));
    if ((tid & 31) == 0) red[tid >> 5] = mx;
    __syncthreads();
    const float m = fmaxf(fmaxf(fmaxf(red[0], red[1]), fmaxf(red[2], red[3])),
                          fmaxf(fmaxf(red[4], red[5]), fmaxf(red[6], red[7])));
    __syncthreads();
    float s = 0.0f;
#pragma unroll
    for (int i = 0; i < 4; i++) { v[i] = expf(v[i] - m); s += v[i]; }
#pragma unroll
    for (int o = 16; o; o >>= 1) s += __shfl_xor_sync(0xffffffffu, s, o);
    if ((tid & 31) == 0) red[tid >> 5] = s;
    __syncthreads();
    const float inv = 1.0f / (red[0] + red[1] + red[2] + red[3] +
                              red[4] + red[5] + red[6] + red[7]);
#pragma unroll
    for (int i = 0; i < 4; i++) p[tid + (i << 8)] = v[i] * inv;
}

// ---------------- enc [S,B,H] -> encT [b][h][s] (fp32 tiled transpose) ----------------
__global__ void transpose_enc(const float* __restrict__ enc, float* __restrict__ encT)
{
    __shared__ float t[32][33];
    const int b  = blockIdx.z;
    const int s0 = blockIdx.x << 5;
    const int h0 = blockIdx.y << 5;
    const int tx = threadIdx.x, ty = threadIdx.y;  // 32x8
#pragma unroll
    for (int j = 0; j < 4; ++j) {
        const int s = s0 + ty + j * 8;
        t[ty + j * 8][tx] = enc[(long)s * 32768 + b * 1024 + h0 + tx];
    }
    __syncthreads();
#pragma unroll
    for (int j = 0; j < 4; ++j) {
        const int h = h0 + ty + j * 8;
        encT[((long)b << 20) + ((long)h << 10) + s0 + tx] = t[tx][ty + j * 8];
    }
}

// ---------------- launch ----------------
extern "C" void kernel_launch(void* const* d_in, const int* in_sizes, int n_in,
                              void* d_out, int out_size)
{
    const float* query = (const float*)d_in[0];  // [B,T,H]
    const float* enc   = (const float*)d_in[1];  // [S,B,H]
    const float* W_in  = (const float*)d_in[3];  // [H,H]
    const float* W_out = (const float*)d_in[4];  // [H,2H]
    const float* b_out = (const float*)d_in[5];  // [H]
    float* out = (float*)d_out;                  // [B,T,H]

    float *Z, *S, *Cc, *encT;
    cudaGetSymbolAddress((void**)&Z, g_Z);
    cudaGetSymbolAddress((void**)&S, g_S);
    cudaGetSymbolAddress((void**)&Cc, g_C);
    cudaGetSymbolAddress((void**)&encT, g_encT);

    const int SM3 = 1024 + 2 * 6 * 16384;  // 197,632 B
    const int SM2 = 1024 + 2 * 4 * 16384;  // 132,096 B
    cudaFuncSetAttribute(mma_gemm<3, 1, 0>, cudaFuncAttributeMaxDynamicSharedMemorySize, SM3);
    cudaFuncSetAttribute(mma_gemm<2, 1, 0>, cudaFuncAttributeMaxDynamicSharedMemorySize, SM2);
    cudaFuncSetAttribute(mma_gemm<2, 2, 1>, cudaFuncAttributeMaxDynamicSharedMemorySize, SM2);

    // encT for GEMM4 (independent of GEMMs 1-2; runs first)
    transpose_enc<<<dim3(32, 32, 32), dim3(32, 8)>>>(enc, encT);

    // 1) Z = Q @ W_in^T   [16384 x 1024], K=1024   (split-3: softmax-path precision)
    mma_gemm<3, 1, 0><<<dim3(8, 128, 1), 256, SM3>>>(
        query, W_in, nullptr, nullptr, 16, 1024, 1024, 0, 0, 0, Z, 1024, nullptr);

    // 2) scores[b] = Z[b] @ enc[:,b,:]^T   (batched; rows are s, k-contig in enc)
    mma_gemm<3, 1, 0><<<dim3(8, 4, 32), 256, SM3>>>(
        Z, enc, nullptr, nullptr, 16, 1024, 32768,
        512L * 1024, 1024, 512L * 1024, S, 1024, nullptr);

    // 3) softmax rows (with ==0 -> -inf quirk)
    softmax_kernel<<<16384, 256>>>(S);

    // 4) c[b] = P[b] @ encT[b]^T  (split-2 is enough post-softmax)
    mma_gemm<2, 1, 0><<<dim3(8, 4, 32), 256, SM2>>>(
        S, encT, nullptr, nullptr, 16, 1024, 1024,
        512L * 1024, 1024L * 1024, 512L * 1024, Cc, 1024, nullptr);

    // 5) out = tanh(C @ Wout1^T + Q @ Wout2^T + b)   (2 segments, K=2048 total)
    mma_gemm<2, 2, 1><<<dim3(8, 128, 1), 256, SM2>>>(
        Cc, W_out, query, W_out + 1024, 16, 1024, 2048, 0, 0, 0, out, 1024, b_out);
}